// round 14
// baseline (speedup 1.0000x reference)
#include <cuda_runtime.h>
#include <cuda_fp16.h>
#include <cstdint>

#define B_   8
#define HWN  4096
#define C3   768
#define CATT 512

// fp32 intermediates
__device__ float g_qkv[B_ * C3 * HWN];
__device__ float g_pw [B_ * C3 * HWN];
__device__ float g_kvp[B_ * 64][4][72];   // per-chunk kv partials

// fp16 split planes (GEMM operands)
__device__ __half g_xh [B_ * 256 * HWN];
__device__ __half g_xl [B_ * 256 * HWN];
__device__ __half g_ath[B_ * CATT * HWN];
__device__ __half g_atl[B_ * CATT * HWN];
__device__ __half g_wqh[768 * 256];
__device__ __half g_wql[768 * 256];
__device__ __half g_wph[256 * 512];
__device__ __half g_wpl[256 * 512];

// ===========================================================================
// helpers
// ===========================================================================
__device__ __forceinline__ uint32_t smem_u32(const void* p) {
    uint32_t a;
    asm("{ .reg .u64 t; cvta.to.shared.u64 t, %1; cvt.u32.u64 %0, t; }"
        : "=r"(a) : "l"(p));
    return a;
}
__device__ __forceinline__ void cpa16(uint32_t dst, const void* src) {
    asm volatile("cp.async.cg.shared.global [%0], [%1], 16;"
                 :: "r"(dst), "l"(src) : "memory");
}
#define CP_COMMIT() asm volatile("cp.async.commit_group;" ::: "memory")
#define CP_WAIT1()  asm volatile("cp.async.wait_group 1;" ::: "memory")

#define LDSM(r0,r1,r2,r3,a) \
    asm volatile("ldmatrix.sync.aligned.m8n8.x4.shared.b16 {%0,%1,%2,%3}, [%4];" \
        : "=r"(r0),"=r"(r1),"=r"(r2),"=r"(r3) : "r"(a))
#define LDSMT(r0,r1,r2,r3,a) \
    asm volatile("ldmatrix.sync.aligned.m8n8.x4.trans.shared.b16 {%0,%1,%2,%3}, [%4];" \
        : "=r"(r0),"=r"(r1),"=r"(r2),"=r"(r3) : "r"(a))
#define MMA(acc_, a_, b0_, b1_) \
    asm volatile("mma.sync.aligned.m16n8k16.row.col.f32.f16.f16.f32 " \
        "{%0,%1,%2,%3}, {%4,%5,%6,%7}, {%8,%9}, {%0,%1,%2,%3};" \
        : "+f"(acc_[0]), "+f"(acc_[1]), "+f"(acc_[2]), "+f"(acc_[3]) \
        : "r"(a_[0]), "r"(a_[1]), "r"(a_[2]), "r"(a_[3]), "r"(b0_), "r"(b1_))

// ===========================================================================
// merged split: fp32 -> fp16 hi/lo planes for x, w_qkv, w_proj in one launch.
// ===========================================================================
#define NX4 ((B_ * 256 * HWN) / 4)
#define NQ4 ((768 * 256) / 4)
#define NP4 ((256 * 512) / 4)

__device__ __forceinline__ void split4(const float* __restrict__ src,
                                       __half2* __restrict__ h2,
                                       __half2* __restrict__ l2, int i)
{
    float4 v = reinterpret_cast<const float4*>(src)[i];
    float f[4] = {v.x, v.y, v.z, v.w};
    __half hh[4], ll[4];
#pragma unroll
    for (int j = 0; j < 4; j++) {
        hh[j] = __float2half_rn(f[j]);
        ll[j] = __float2half_rn(f[j] - __half2float(hh[j]));
    }
    h2[2 * i]     = __halves2half2(hh[0], hh[1]);
    h2[2 * i + 1] = __halves2half2(hh[2], hh[3]);
    l2[2 * i]     = __halves2half2(ll[0], ll[1]);
    l2[2 * i + 1] = __halves2half2(ll[2], ll[3]);
}

__global__ __launch_bounds__(256) void split_all_k(
    const float* __restrict__ x, const float* __restrict__ wq,
    const float* __restrict__ wp,
    __half2* xh, __half2* xl, __half2* qh, __half2* ql,
    __half2* ph, __half2* pl)
{
    int i = blockIdx.x * 256 + threadIdx.x;
    if (i < NX4)                   split4(x,  xh, xl, i);
    else if (i < NX4 + NQ4)        split4(wq, qh, ql, i - NX4);
    else if (i < NX4 + NQ4 + NP4)  split4(wp, ph, pl, i - NX4 - NQ4);
}

// ===========================================================================
// fp16x2-split GEMM, K-tile 32, templated M-tile (R12 proven config).
// 8 warps (2m x 4n), warp tile (MT*16) x 32, 3-stage cp.async.
// ===========================================================================
template<int MT>
__global__ __launch_bounds__(256, 2) void gemm_fp16x2(
    const __half* __restrict__ Ah, const __half* __restrict__ Al,
    const __half* __restrict__ Bh, const __half* __restrict__ Bl,
    float* __restrict__ Csrc, int M, int N, int K,
    const float* __restrict__ gamma, const float* __restrict__ beta,
    const float* __restrict__ mean,  const float* __restrict__ var)
{
    constexpr int RT    = MT * 32;
    constexpr int APL   = RT * 64;
    constexpr int AOFFL = APL;
    constexpr int BOFFH = 2 * APL;
    constexpr int BOFFL = 2 * APL + 8704;
    constexpr int STGB  = 2 * APL + 2 * 8704;

    extern __shared__ char dsm[];
    const uint32_t sb = smem_u32(dsm);

    const int tid = threadIdx.x, lane = tid & 31, warp = tid >> 5;
    const int wm = warp >> 2, wn = warp & 3;
    const int gr = lane >> 2, gc = lane & 3;

    const size_t bz = (size_t)blockIdx.z * K * N;
    float* Cm = Csrc + (size_t)blockIdx.z * M * N;

    const __half* aBaseH = Ah + (size_t)(blockIdx.y * RT) * K;
    const __half* aBaseL = Al + (size_t)(blockIdx.y * RT) * K;
    const __half* bSrcH = Bh + bz + blockIdx.x * 128;
    const __half* bSrcL = Bl + bz + blockIdx.x * 128;

    auto issue = [&](int kt) {
        uint32_t st = sb + (kt % 3) * STGB;
        int kbase = kt * 32;
        for (int c = tid; c < RT * 4; c += 256) {
            int row = c >> 2, seg = c & 3;
            uint32_t ad = st + row * 64 + ((seg ^ ((row >> 1) & 3)) * 16);
            const size_t so = (size_t)row * K + kbase + seg * 8;
            cpa16(ad,         aBaseH + so);
            cpa16(ad + AOFFL, aBaseL + so);
        }
#pragma unroll
        for (int j = 0; j < 2; j++) {
            int q = tid * 2 + j;
            int krow = q >> 4, seg = q & 15;
            uint32_t bd = st + krow * 272 + seg * 16;
            const size_t so = (size_t)(kbase + krow) * N + seg * 8;
            cpa16(bd + BOFFH, bSrcH + so);
            cpa16(bd + BOFFL, bSrcL + so);
        }
    };

    float acc[MT][4][4];
#pragma unroll
    for (int mt = 0; mt < MT; mt++)
#pragma unroll
        for (int nt = 0; nt < 4; nt++)
#pragma unroll
            for (int i = 0; i < 4; i++) acc[mt][nt][i] = 0.f;

    const int nk = K / 32;
    issue(0); CP_COMMIT();
    issue(1); CP_COMMIT();

    const uint32_t brow = (lane & 7) + 8 * ((lane >> 3) & 1);
    const uint32_t bn   = 8 * (lane >> 4);
    const int arl = lane & 15;
    const int ach = lane >> 4;

    for (int kt = 0; kt < nk; kt++) {
        CP_WAIT1();
        __syncthreads();
        if (kt + 2 < nk) issue(kt + 2);
        CP_COMMIT();

        const uint32_t st = sb + (kt % 3) * STGB;

#pragma unroll
        for (int ks = 0; ks < 2; ks++) {
            uint32_t bfr[2][2][4];
#pragma unroll
            for (int ng = 0; ng < 2; ng++) {
                uint32_t ad = st + BOFFH + (ks * 16 + brow) * 272
                            + (wn * 32 + ng * 16 + bn) * 2;
                LDSMT(bfr[0][ng][0], bfr[0][ng][1], bfr[0][ng][2], bfr[0][ng][3], ad);
                LDSMT(bfr[1][ng][0], bfr[1][ng][1], bfr[1][ng][2], bfr[1][ng][3],
                      ad + (BOFFL - BOFFH));
            }
#pragma unroll
            for (int mt = 0; mt < MT; mt++) {
                int rA = wm * (MT * 16) + mt * 16 + arl;
                int c = ks * 2 + ach;
                uint32_t ma = st + rA * 64 + ((c ^ ((rA >> 1) & 3)) * 16);
                uint32_t ah[4], al[4];
                LDSM(ah[0], ah[1], ah[2], ah[3], ma);
                LDSM(al[0], al[1], al[2], al[3], ma + AOFFL);
#pragma unroll
                for (int nt = 0; nt < 4; nt++)
                    MMA(acc[mt][nt], ah, bfr[1][nt >> 1][2 * (nt & 1)],
                        bfr[1][nt >> 1][2 * (nt & 1) + 1]);
#pragma unroll
                for (int nt = 0; nt < 4; nt++)
                    MMA(acc[mt][nt], al, bfr[0][nt >> 1][2 * (nt & 1)],
                        bfr[0][nt >> 1][2 * (nt & 1) + 1]);
#pragma unroll
                for (int nt = 0; nt < 4; nt++)
                    MMA(acc[mt][nt], ah, bfr[0][nt >> 1][2 * (nt & 1)],
                        bfr[0][nt >> 1][2 * (nt & 1) + 1]);
            }
        }
    }

    // epilogue
#pragma unroll
    for (int mt = 0; mt < MT; mt++) {
        int r0 = blockIdx.y * RT + wm * (MT * 16) + mt * 16 + gr;
        int r1 = r0 + 8;
        float sc0 = 1.f, bi0 = 0.f, sc1 = 1.f, bi1 = 0.f;
        if (gamma) {
            float i0 = gamma[r0] * rsqrtf(var[r0] + 1e-5f);
            float i1 = gamma[r1] * rsqrtf(var[r1] + 1e-5f);
            sc0 = i0; bi0 = beta[r0] - mean[r0] * i0;
            sc1 = i1; bi1 = beta[r1] - mean[r1] * i1;
        }
#pragma unroll
        for (int nt = 0; nt < 4; nt++) {
            int col = blockIdx.x * 128 + wn * 32 + nt * 8 + gc * 2;
            float2 v0 = make_float2(acc[mt][nt][0] * sc0 + bi0, acc[mt][nt][1] * sc0 + bi0);
            float2 v1 = make_float2(acc[mt][nt][2] * sc1 + bi1, acc[mt][nt][3] * sc1 + bi1);
            *reinterpret_cast<float2*>(Cm + (size_t)r0 * N + col) = v0;
            *reinterpret_cast<float2*>(Cm + (size_t)r1 * N + col) = v1;
        }
    }
}

// ===========================================================================
// Fused depthwise 5x5 (pad 2) + grouped pointwise (best config).
// ===========================================================================
__global__ __launch_bounds__(256) void dwpw_k(const float* __restrict__ w_dw,
                                              const float* __restrict__ w_pw)
{
    const int bz = blockIdx.z;
    const int g = bz % 96, b = bz / 96;

    __shared__ float t[8][36][40];
    __shared__ float wd[8][25];
    __shared__ float wp[64];

    const int tid = threadIdx.x;
    const int tx4 = (tid & 7) * 4, ty = tid >> 3;
    const int x0 = (blockIdx.x & 1) * 32, y0 = (blockIdx.x >> 1) * 32;

    const float* ip = g_qkv + ((size_t)b * C3 + g * 8) * HWN;

    if (tid < 200) wd[tid / 25][tid % 25] = w_dw[g * 200 + tid];
    if (tid < 64)  wp[tid] = w_pw[g * 64 + tid];

    for (int i = tid; i < 2880; i += 256) {
        int ch = i / 360, rem = i % 360;
        int yy = rem / 10, vx = rem % 10;
        int gy = y0 + yy - 2, gx = x0 + vx * 4 - 4;
        float4 v = make_float4(0.f, 0.f, 0.f, 0.f);
        if ((unsigned)gy < 64u && (unsigned)gx < 64u)
            v = *reinterpret_cast<const float4*>(ip + ch * HWN + gy * 64 + gx);
        *reinterpret_cast<float4*>(&t[ch][yy][vx * 4]) = v;
    }
    __syncthreads();

    float dv[8][4];
#pragma unroll
    for (int ch = 0; ch < 8; ch++) {
        float a0 = 0.f, a1 = 0.f, a2 = 0.f, a3 = 0.f;
#pragma unroll
        for (int ky = 0; ky < 5; ky++) {
            const float* row = &t[ch][ty + ky][tx4 + 2];
            float r[8];
#pragma unroll
            for (int i = 0; i < 8; i++) r[i] = row[i];
#pragma unroll
            for (int kx = 0; kx < 5; kx++) {
                float w = wd[ch][ky * 5 + kx];
                a0 += r[kx] * w; a1 += r[kx + 1] * w;
                a2 += r[kx + 2] * w; a3 += r[kx + 3] * w;
            }
        }
        dv[ch][0] = a0; dv[ch][1] = a1; dv[ch][2] = a2; dv[ch][3] = a3;
    }

    float* op = g_pw + ((size_t)b * C3 + g * 8) * HWN + (y0 + ty) * 64 + x0 + tx4;
#pragma unroll
    for (int o = 0; o < 8; o++) {
        float4 s = make_float4(0.f, 0.f, 0.f, 0.f);
#pragma unroll
        for (int i = 0; i < 8; i++) {
            float w = wp[o * 8 + i];
            s.x += dv[i][0] * w; s.y += dv[i][1] * w;
            s.z += dv[i][2] * w; s.w += dv[i][3] * w;
        }
        *reinterpret_cast<float4*>(op + o * HWN) = s;
    }
}

// ===========================================================================
// Attention pass 1: warp-split kv rows. Each warp owns 2 d-rows (18 accs);
// iterates over all 1024 px of its chunk. 128 thr, 4 chunks.
// ===========================================================================
__global__ __launch_bounds__(128) void att1_k()
{
    const int bh = blockIdx.x;
    const int h = bh & 63, b = bh >> 6;

    const float* src = (h < 32)
        ? g_qkv + ((size_t)b * C3 + h * 24) * HWN
        : g_pw  + ((size_t)b * C3 + (h - 32) * 24) * HWN;

    const int warp = threadIdx.x >> 5, lane = threadIdx.x & 31;
    const int d0 = warp * 2;
    const float* k0p = src + (8 + d0) * HWN;
    const float* k1p = src + (9 + d0) * HWN;

    float acc[2][9];
#pragma unroll
    for (int i = 0; i < 2; i++)
#pragma unroll
        for (int j = 0; j < 9; j++) acc[i][j] = 0.f;

    const int base = blockIdx.y * 1024;
#pragma unroll
    for (int it = 0; it < 8; it++) {
        const int hw = base + it * 128 + lane * 4;
        float4 ka = *reinterpret_cast<const float4*>(k0p + hw);
        float4 kb = *reinterpret_cast<const float4*>(k1p + hw);
        ka = make_float4(fmaxf(ka.x, 0.f), fmaxf(ka.y, 0.f),
                         fmaxf(ka.z, 0.f), fmaxf(ka.w, 0.f));
        kb = make_float4(fmaxf(kb.x, 0.f), fmaxf(kb.y, 0.f),
                         fmaxf(kb.z, 0.f), fmaxf(kb.w, 0.f));
#pragma unroll
        for (int e = 0; e < 8; e++) {
            float4 v = *reinterpret_cast<const float4*>(src + (16 + e) * HWN + hw);
            acc[0][e] += ka.x * v.x + ka.y * v.y + ka.z * v.z + ka.w * v.w;
            acc[1][e] += kb.x * v.x + kb.y * v.y + kb.z * v.z + kb.w * v.w;
        }
        acc[0][8] += ka.x + ka.y + ka.z + ka.w;
        acc[1][8] += kb.x + kb.y + kb.z + kb.w;
    }

    // warp reduce 18 values, lane 0 writes
#pragma unroll
    for (int i = 0; i < 18; i++) {
        float v = acc[i / 9][i % 9];
#pragma unroll
        for (int o = 16; o > 0; o >>= 1) v += __shfl_down_sync(0xffffffffu, v, o);
        if (lane == 0)
            g_kvp[bh][blockIdx.y][(d0 + i / 9) * 9 + (i % 9)] = v;
    }
}

// ===========================================================================
// Attention pass 2 (R12 config): out = relu(q) @ kv, normalize; fp16 planes.
// 128 thr, 8 chunks, 4 px/thread.
// ===========================================================================
__global__ __launch_bounds__(128) void att2_k()
{
    const int bh = blockIdx.x;
    const int h = bh & 63, b = bh >> 6;

    const float* src = (h < 32)
        ? g_qkv + ((size_t)b * C3 + h * 24) * HWN
        : g_pw  + ((size_t)b * C3 + (h - 32) * 24) * HWN;

    __shared__ float kvm[72];
    if (threadIdx.x < 72) {
        float s = 0.f;
#pragma unroll
        for (int c = 0; c < 4; c++) s += g_kvp[bh][c][threadIdx.x];
        kvm[threadIdx.x] = s;
    }
    __syncthreads();

    const size_t dbase = ((size_t)b * CATT + h * 8) * HWN;
    const int hw = blockIdx.y * 512 + threadIdx.x * 4;

    float4 q[8];
#pragma unroll
    for (int d = 0; d < 8; d++) {
        float4 v = *reinterpret_cast<const float4*>(src + d * HWN + hw);
        q[d] = make_float4(fmaxf(v.x, 0.f), fmaxf(v.y, 0.f),
                           fmaxf(v.z, 0.f), fmaxf(v.w, 0.f));
    }
    float4 den = make_float4(0.f, 0.f, 0.f, 0.f);
#pragma unroll
    for (int d = 0; d < 8; d++) {
        float w = kvm[d * 9 + 8];
        den.x += q[d].x * w; den.y += q[d].y * w;
        den.z += q[d].z * w; den.w += q[d].w * w;
    }
    float4 inv;
    inv.x = 1.f / (den.x + 1e-15f); inv.y = 1.f / (den.y + 1e-15f);
    inv.z = 1.f / (den.z + 1e-15f); inv.w = 1.f / (den.w + 1e-15f);

#pragma unroll
    for (int e = 0; e < 8; e++) {
        float4 o = make_float4(0.f, 0.f, 0.f, 0.f);
#pragma unroll
        for (int d = 0; d < 8; d++) {
            float w = kvm[d * 9 + e];
            o.x += q[d].x * w; o.y += q[d].y * w;
            o.z += q[d].z * w; o.w += q[d].w * w;
        }
        float val[4] = {o.x * inv.x, o.y * inv.y, o.z * inv.z, o.w * inv.w};
        __half hh[4], ll[4];
#pragma unroll
        for (int j = 0; j < 4; j++) {
            hh[j] = __float2half_rn(val[j]);
            ll[j] = __float2half_rn(val[j] - __half2float(hh[j]));
        }
        __half2* ph = reinterpret_cast<__half2*>(&g_ath[dbase + e * HWN + hw]);
        __half2* pl = reinterpret_cast<__half2*>(&g_atl[dbase + e * HWN + hw]);
        ph[0] = __halves2half2(hh[0], hh[1]);
        ph[1] = __halves2half2(hh[2], hh[3]);
        pl[0] = __halves2half2(ll[0], ll[1]);
        pl[1] = __halves2half2(ll[2], ll[3]);
    }
}

// ===========================================================================
extern "C" void kernel_launch(void* const* d_in, const int* in_sizes, int n_in,
                              void* d_out, int out_size)
{
    const float* x      = (const float*)d_in[0];
    const float* w_qkv  = (const float*)d_in[1];
    const float* w_dw   = (const float*)d_in[2];
    const float* w_pw   = (const float*)d_in[3];
    const float* w_proj = (const float*)d_in[4];
    const float* gm     = (const float*)d_in[5];
    const float* bt     = (const float*)d_in[6];
    const float* mn     = (const float*)d_in[7];
    const float* vr     = (const float*)d_in[8];
    float* out = (float*)d_out;

    __half *xh, *xl, *ath, *atl, *wqh, *wql, *wph, *wpl;
    float* qkv;
    cudaGetSymbolAddress((void**)&qkv, g_qkv);
    cudaGetSymbolAddress((void**)&xh,  g_xh);
    cudaGetSymbolAddress((void**)&xl,  g_xl);
    cudaGetSymbolAddress((void**)&ath, g_ath);
    cudaGetSymbolAddress((void**)&atl, g_atl);
    cudaGetSymbolAddress((void**)&wqh, g_wqh);
    cudaGetSymbolAddress((void**)&wql, g_wql);
    cudaGetSymbolAddress((void**)&wph, g_wph);
    cudaGetSymbolAddress((void**)&wpl, g_wpl);

    cudaFuncSetAttribute(gemm_fp16x2<3>, cudaFuncAttributeMaxDynamicSharedMemorySize,
                         89088);
    cudaFuncSetAttribute(gemm_fp16x2<4>, cudaFuncAttributeMaxDynamicSharedMemorySize,
                         101376);

    // 0) one merged split launch (x, w_qkv, w_proj)
    int total4 = NX4 + NQ4 + NP4;
    split_all_k<<<(total4 + 255) / 256, 256>>>(
        x, w_qkv, w_proj,
        (__half2*)xh, (__half2*)xl, (__half2*)wqh, (__half2*)wql,
        (__half2*)wph, (__half2*)wpl);

    // 1) qkv GEMM  [TM=96, R12 proven config]
    gemm_fp16x2<3><<<dim3(32, 8, B_), 256, 89088>>>(
        wqh, wql, xh, xl, qkv, 768, HWN, 256, nullptr, nullptr, nullptr, nullptr);
    // 2) fused dw 5x5 + grouped pw
    dwpw_k<<<dim3(4, 1, B_ * 96), 256>>>(w_dw, w_pw);
    // 3) attention
    att1_k<<<dim3(B_ * 64, 4), 128>>>();
    att2_k<<<dim3(B_ * 64, 8), 128>>>();
    // 4) proj + BN  [TM=128, R12 proven config]
    gemm_fp16x2<4><<<dim3(32, 2, B_), 256, 101376>>>(
        wph, wpl, ath, atl, out, 256, HWN, 512, gm, bt, mn, vr);
}

// round 15
// speedup vs baseline: 1.1287x; 1.1287x over previous
#include <cuda_runtime.h>
#include <cuda_fp16.h>
#include <cstdint>

#define B_   8
#define HWN  4096
#define C3   768
#define CATT 512

// half intermediates (dw/attention corridor)
__device__ __half g_qkvh[B_ * C3 * HWN];
__device__ __half g_pwh [B_ * C3 * HWN];
__device__ float  g_kvp[B_ * 64][4][72];

// fp16 split planes (GEMM operands)
__device__ __half g_xh [B_ * 256 * HWN];
__device__ __half g_xl [B_ * 256 * HWN];
__device__ __half g_ath[B_ * CATT * HWN];
__device__ __half g_atl[B_ * CATT * HWN];
__device__ __half g_wqh[768 * 256];
__device__ __half g_wql[768 * 256];
__device__ __half g_wph[256 * 512];
__device__ __half g_wpl[256 * 512];

// ===========================================================================
// helpers
// ===========================================================================
__device__ __forceinline__ uint32_t smem_u32(const void* p) {
    uint32_t a;
    asm("{ .reg .u64 t; cvta.to.shared.u64 t, %1; cvt.u32.u64 %0, t; }"
        : "=r"(a) : "l"(p));
    return a;
}
__device__ __forceinline__ void cpa16(uint32_t dst, const void* src) {
    asm volatile("cp.async.cg.shared.global [%0], [%1], 16;"
                 :: "r"(dst), "l"(src) : "memory");
}
#define CP_COMMIT() asm volatile("cp.async.commit_group;" ::: "memory")
#define CP_WAIT1()  asm volatile("cp.async.wait_group 1;" ::: "memory")

#define LDSM(r0,r1,r2,r3,a) \
    asm volatile("ldmatrix.sync.aligned.m8n8.x4.shared.b16 {%0,%1,%2,%3}, [%4];" \
        : "=r"(r0),"=r"(r1),"=r"(r2),"=r"(r3) : "r"(a))
#define LDSMT(r0,r1,r2,r3,a) \
    asm volatile("ldmatrix.sync.aligned.m8n8.x4.trans.shared.b16 {%0,%1,%2,%3}, [%4];" \
        : "=r"(r0),"=r"(r1),"=r"(r2),"=r"(r3) : "r"(a))
#define MMA(acc_, a_, b0_, b1_) \
    asm volatile("mma.sync.aligned.m16n8k16.row.col.f32.f16.f16.f32 " \
        "{%0,%1,%2,%3}, {%4,%5,%6,%7}, {%8,%9}, {%0,%1,%2,%3};" \
        : "+f"(acc_[0]), "+f"(acc_[1]), "+f"(acc_[2]), "+f"(acc_[3]) \
        : "r"(a_[0]), "r"(a_[1]), "r"(a_[2]), "r"(a_[3]), "r"(b0_), "r"(b1_))

// load 4 halves -> float4 (8B load)
__device__ __forceinline__ float4 ldh4(const __half* p) {
    uint2 u = *reinterpret_cast<const uint2*>(p);
    __half2 a = *reinterpret_cast<__half2*>(&u.x);
    __half2 b = *reinterpret_cast<__half2*>(&u.y);
    float2 fa = __half22float2(a), fb = __half22float2(b);
    return make_float4(fa.x, fa.y, fb.x, fb.y);
}
__device__ __forceinline__ void sth4(__half* p, float4 v) {
    uint2 u;
    __half2 a = __floats2half2_rn(v.x, v.y);
    __half2 b = __floats2half2_rn(v.z, v.w);
    u.x = *reinterpret_cast<uint32_t*>(&a);
    u.y = *reinterpret_cast<uint32_t*>(&b);
    *reinterpret_cast<uint2*>(p) = u;
}

// ===========================================================================
// merged split: fp32 -> fp16 hi/lo planes for x, w_qkv, w_proj.
// ===========================================================================
#define NX4 ((B_ * 256 * HWN) / 4)
#define NQ4 ((768 * 256) / 4)
#define NP4 ((256 * 512) / 4)

__device__ __forceinline__ void split4(const float* __restrict__ src,
                                       __half2* __restrict__ h2,
                                       __half2* __restrict__ l2, int i)
{
    float4 v = reinterpret_cast<const float4*>(src)[i];
    float f[4] = {v.x, v.y, v.z, v.w};
    __half hh[4], ll[4];
#pragma unroll
    for (int j = 0; j < 4; j++) {
        hh[j] = __float2half_rn(f[j]);
        ll[j] = __float2half_rn(f[j] - __half2float(hh[j]));
    }
    h2[2 * i]     = __halves2half2(hh[0], hh[1]);
    h2[2 * i + 1] = __halves2half2(hh[2], hh[3]);
    l2[2 * i]     = __halves2half2(ll[0], ll[1]);
    l2[2 * i + 1] = __halves2half2(ll[2], ll[3]);
}

__global__ __launch_bounds__(256) void split_all_k(
    const float* __restrict__ x, const float* __restrict__ wq,
    const float* __restrict__ wp,
    __half2* xh, __half2* xl, __half2* qh, __half2* ql,
    __half2* ph, __half2* pl)
{
    int i = blockIdx.x * 256 + threadIdx.x;
    if (i < NX4)                   split4(x,  xh, xl, i);
    else if (i < NX4 + NQ4)        split4(wq, qh, ql, i - NX4);
    else if (i < NX4 + NQ4 + NP4)  split4(wp, ph, pl, i - NX4 - NQ4);
}

// ===========================================================================
// fp16x2-split GEMM, K-tile 32, templated M-tile; WH: write __half output.
// 8 warps (2m x 4n), 3-stage cp.async. (R12 proven config)
// ===========================================================================
template<int MT, bool WH>
__global__ __launch_bounds__(256, 2) void gemm_fp16x2(
    const __half* __restrict__ Ah, const __half* __restrict__ Al,
    const __half* __restrict__ Bh, const __half* __restrict__ Bl,
    void* __restrict__ Csrc, int M, int N, int K,
    const float* __restrict__ gamma, const float* __restrict__ beta,
    const float* __restrict__ mean,  const float* __restrict__ var)
{
    constexpr int RT    = MT * 32;
    constexpr int APL   = RT * 64;
    constexpr int AOFFL = APL;
    constexpr int BOFFH = 2 * APL;
    constexpr int BOFFL = 2 * APL + 8704;
    constexpr int STGB  = 2 * APL + 2 * 8704;

    extern __shared__ char dsm[];
    const uint32_t sb = smem_u32(dsm);

    const int tid = threadIdx.x, lane = tid & 31, warp = tid >> 5;
    const int wm = warp >> 2, wn = warp & 3;
    const int gr = lane >> 2, gc = lane & 3;

    const size_t bz = (size_t)blockIdx.z * K * N;

    const __half* aBaseH = Ah + (size_t)(blockIdx.y * RT) * K;
    const __half* aBaseL = Al + (size_t)(blockIdx.y * RT) * K;
    const __half* bSrcH = Bh + bz + blockIdx.x * 128;
    const __half* bSrcL = Bl + bz + blockIdx.x * 128;

    auto issue = [&](int kt) {
        uint32_t st = sb + (kt % 3) * STGB;
        int kbase = kt * 32;
        for (int c = tid; c < RT * 4; c += 256) {
            int row = c >> 2, seg = c & 3;
            uint32_t ad = st + row * 64 + ((seg ^ ((row >> 1) & 3)) * 16);
            const size_t so = (size_t)row * K + kbase + seg * 8;
            cpa16(ad,         aBaseH + so);
            cpa16(ad + AOFFL, aBaseL + so);
        }
#pragma unroll
        for (int j = 0; j < 2; j++) {
            int q = tid * 2 + j;
            int krow = q >> 4, seg = q & 15;
            uint32_t bd = st + krow * 272 + seg * 16;
            const size_t so = (size_t)(kbase + krow) * N + seg * 8;
            cpa16(bd + BOFFH, bSrcH + so);
            cpa16(bd + BOFFL, bSrcL + so);
        }
    };

    float acc[MT][4][4];
#pragma unroll
    for (int mt = 0; mt < MT; mt++)
#pragma unroll
        for (int nt = 0; nt < 4; nt++)
#pragma unroll
            for (int i = 0; i < 4; i++) acc[mt][nt][i] = 0.f;

    const int nk = K / 32;
    issue(0); CP_COMMIT();
    issue(1); CP_COMMIT();

    const uint32_t brow = (lane & 7) + 8 * ((lane >> 3) & 1);
    const uint32_t bn   = 8 * (lane >> 4);
    const int arl = lane & 15;
    const int ach = lane >> 4;

    for (int kt = 0; kt < nk; kt++) {
        CP_WAIT1();
        __syncthreads();
        if (kt + 2 < nk) issue(kt + 2);
        CP_COMMIT();

        const uint32_t st = sb + (kt % 3) * STGB;

#pragma unroll
        for (int ks = 0; ks < 2; ks++) {
            uint32_t bfr[2][2][4];
#pragma unroll
            for (int ng = 0; ng < 2; ng++) {
                uint32_t ad = st + BOFFH + (ks * 16 + brow) * 272
                            + (wn * 32 + ng * 16 + bn) * 2;
                LDSMT(bfr[0][ng][0], bfr[0][ng][1], bfr[0][ng][2], bfr[0][ng][3], ad);
                LDSMT(bfr[1][ng][0], bfr[1][ng][1], bfr[1][ng][2], bfr[1][ng][3],
                      ad + (BOFFL - BOFFH));
            }
#pragma unroll
            for (int mt = 0; mt < MT; mt++) {
                int rA = wm * (MT * 16) + mt * 16 + arl;
                int c = ks * 2 + ach;
                uint32_t ma = st + rA * 64 + ((c ^ ((rA >> 1) & 3)) * 16);
                uint32_t ah[4], al[4];
                LDSM(ah[0], ah[1], ah[2], ah[3], ma);
                LDSM(al[0], al[1], al[2], al[3], ma + AOFFL);
#pragma unroll
                for (int nt = 0; nt < 4; nt++)
                    MMA(acc[mt][nt], ah, bfr[1][nt >> 1][2 * (nt & 1)],
                        bfr[1][nt >> 1][2 * (nt & 1) + 1]);
#pragma unroll
                for (int nt = 0; nt < 4; nt++)
                    MMA(acc[mt][nt], al, bfr[0][nt >> 1][2 * (nt & 1)],
                        bfr[0][nt >> 1][2 * (nt & 1) + 1]);
#pragma unroll
                for (int nt = 0; nt < 4; nt++)
                    MMA(acc[mt][nt], ah, bfr[0][nt >> 1][2 * (nt & 1)],
                        bfr[0][nt >> 1][2 * (nt & 1) + 1]);
            }
        }
    }

    // epilogue
#pragma unroll
    for (int mt = 0; mt < MT; mt++) {
        int r0 = blockIdx.y * RT + wm * (MT * 16) + mt * 16 + gr;
        int r1 = r0 + 8;
        float sc0 = 1.f, bi0 = 0.f, sc1 = 1.f, bi1 = 0.f;
        if (gamma) {
            float i0 = gamma[r0] * rsqrtf(var[r0] + 1e-5f);
            float i1 = gamma[r1] * rsqrtf(var[r1] + 1e-5f);
            sc0 = i0; bi0 = beta[r0] - mean[r0] * i0;
            sc1 = i1; bi1 = beta[r1] - mean[r1] * i1;
        }
#pragma unroll
        for (int nt = 0; nt < 4; nt++) {
            int col = blockIdx.x * 128 + wn * 32 + nt * 8 + gc * 2;
            float v00 = acc[mt][nt][0] * sc0 + bi0, v01 = acc[mt][nt][1] * sc0 + bi0;
            float v10 = acc[mt][nt][2] * sc1 + bi1, v11 = acc[mt][nt][3] * sc1 + bi1;
            if (WH) {
                __half* Cm = (__half*)Csrc + (size_t)blockIdx.z * M * N;
                *reinterpret_cast<__half2*>(Cm + (size_t)r0 * N + col) =
                    __floats2half2_rn(v00, v01);
                *reinterpret_cast<__half2*>(Cm + (size_t)r1 * N + col) =
                    __floats2half2_rn(v10, v11);
            } else {
                float* Cm = (float*)Csrc + (size_t)blockIdx.z * M * N;
                *reinterpret_cast<float2*>(Cm + (size_t)r0 * N + col) =
                    make_float2(v00, v01);
                *reinterpret_cast<float2*>(Cm + (size_t)r1 * N + col) =
                    make_float2(v10, v11);
            }
        }
    }
}

// ===========================================================================
// Fused depthwise 5x5 (pad 2) + grouped pointwise; half in, half out.
// ===========================================================================
__global__ __launch_bounds__(256) void dwpw_k(const float* __restrict__ w_dw,
                                              const float* __restrict__ w_pw)
{
    const int bz = blockIdx.z;
    const int g = bz % 96, b = bz / 96;

    __shared__ float t[8][36][40];
    __shared__ float wd[8][25];
    __shared__ float wp[64];

    const int tid = threadIdx.x;
    const int tx4 = (tid & 7) * 4, ty = tid >> 3;
    const int x0 = (blockIdx.x & 1) * 32, y0 = (blockIdx.x >> 1) * 32;

    const __half* ip = g_qkvh + ((size_t)b * C3 + g * 8) * HWN;

    if (tid < 200) wd[tid / 25][tid % 25] = w_dw[g * 200 + tid];
    if (tid < 64)  wp[tid] = w_pw[g * 64 + tid];

    for (int i = tid; i < 2880; i += 256) {
        int ch = i / 360, rem = i % 360;
        int yy = rem / 10, vx = rem % 10;
        int gy = y0 + yy - 2, gx = x0 + vx * 4 - 4;
        float4 v = make_float4(0.f, 0.f, 0.f, 0.f);
        if ((unsigned)gy < 64u && (unsigned)gx < 64u)
            v = ldh4(ip + ch * HWN + gy * 64 + gx);
        *reinterpret_cast<float4*>(&t[ch][yy][vx * 4]) = v;
    }
    __syncthreads();

    float dv[8][4];
#pragma unroll
    for (int ch = 0; ch < 8; ch++) {
        float a0 = 0.f, a1 = 0.f, a2 = 0.f, a3 = 0.f;
#pragma unroll
        for (int ky = 0; ky < 5; ky++) {
            const float* row = &t[ch][ty + ky][tx4 + 2];
            float r[8];
#pragma unroll
            for (int i = 0; i < 8; i++) r[i] = row[i];
#pragma unroll
            for (int kx = 0; kx < 5; kx++) {
                float w = wd[ch][ky * 5 + kx];
                a0 += r[kx] * w; a1 += r[kx + 1] * w;
                a2 += r[kx + 2] * w; a3 += r[kx + 3] * w;
            }
        }
        dv[ch][0] = a0; dv[ch][1] = a1; dv[ch][2] = a2; dv[ch][3] = a3;
    }

    __half* op = g_pwh + ((size_t)b * C3 + g * 8) * HWN + (y0 + ty) * 64 + x0 + tx4;
#pragma unroll
    for (int o = 0; o < 8; o++) {
        float4 s = make_float4(0.f, 0.f, 0.f, 0.f);
#pragma unroll
        for (int i = 0; i < 8; i++) {
            float w = wp[o * 8 + i];
            s.x += dv[i][0] * w; s.y += dv[i][1] * w;
            s.z += dv[i][2] * w; s.w += dv[i][3] * w;
        }
        sth4(op + o * HWN, s);
    }
}

// ===========================================================================
// Attention pass 1 (R12 structure): 128 thr, 4 chunks, 8 px/thread,
// smem-transpose reduction; half inputs.
// ===========================================================================
__global__ __launch_bounds__(128) void att1_k()
{
    const int bh = blockIdx.x;
    const int h = bh & 63, b = bh >> 6;

    const __half* src = (h < 32)
        ? g_qkvh + ((size_t)b * C3 + h * 24) * HWN
        : g_pwh  + ((size_t)b * C3 + (h - 32) * 24) * HWN;

    float acc[72];
#pragma unroll
    for (int i = 0; i < 72; i++) acc[i] = 0.f;

#pragma unroll
    for (int it = 0; it < 2; it++) {
        const int hw = blockIdx.y * 1024 + it * 512 + threadIdx.x * 4;
        float4 kk[8], vv[8];
#pragma unroll
        for (int d = 0; d < 8; d++) {
            float4 v = ldh4(src + (8 + d) * HWN + hw);
            kk[d] = make_float4(fmaxf(v.x, 0.f), fmaxf(v.y, 0.f),
                                fmaxf(v.z, 0.f), fmaxf(v.w, 0.f));
        }
#pragma unroll
        for (int e = 0; e < 8; e++)
            vv[e] = ldh4(src + (16 + e) * HWN + hw);

#pragma unroll
        for (int d = 0; d < 8; d++) {
#pragma unroll
            for (int e = 0; e < 8; e++)
                acc[d * 9 + e] += kk[d].x * vv[e].x + kk[d].y * vv[e].y
                                + kk[d].z * vv[e].z + kk[d].w * vv[e].w;
            acc[d * 9 + 8] += kk[d].x + kk[d].y + kk[d].z + kk[d].w;
        }
    }

    __shared__ float red[128][73];
#pragma unroll
    for (int i = 0; i < 72; i++) red[threadIdx.x][i] = acc[i];
    __syncthreads();
    if (threadIdx.x < 72) {
        float s = 0.f;
#pragma unroll 16
        for (int t = 0; t < 128; t++) s += red[t][threadIdx.x];
        g_kvp[bh][blockIdx.y][threadIdx.x] = s;
    }
}

// ===========================================================================
// Attention pass 2 (R12 structure): 128 thr, 8 chunks, 4 px/thread;
// half q inputs; fp16 hi/lo plane outputs.
// ===========================================================================
__global__ __launch_bounds__(128) void att2_k()
{
    const int bh = blockIdx.x;
    const int h = bh & 63, b = bh >> 6;

    const __half* src = (h < 32)
        ? g_qkvh + ((size_t)b * C3 + h * 24) * HWN
        : g_pwh  + ((size_t)b * C3 + (h - 32) * 24) * HWN;

    __shared__ float kvm[72];
    if (threadIdx.x < 72) {
        float s = 0.f;
#pragma unroll
        for (int c = 0; c < 4; c++) s += g_kvp[bh][c][threadIdx.x];
        kvm[threadIdx.x] = s;
    }
    __syncthreads();

    const size_t dbase = ((size_t)b * CATT + h * 8) * HWN;
    const int hw = blockIdx.y * 512 + threadIdx.x * 4;

    float4 q[8];
#pragma unroll
    for (int d = 0; d < 8; d++) {
        float4 v = ldh4(src + d * HWN + hw);
        q[d] = make_float4(fmaxf(v.x, 0.f), fmaxf(v.y, 0.f),
                           fmaxf(v.z, 0.f), fmaxf(v.w, 0.f));
    }
    float4 den = make_float4(0.f, 0.f, 0.f, 0.f);
#pragma unroll
    for (int d = 0; d < 8; d++) {
        float w = kvm[d * 9 + 8];
        den.x += q[d].x * w; den.y += q[d].y * w;
        den.z += q[d].z * w; den.w += q[d].w * w;
    }
    float4 inv;
    inv.x = 1.f / (den.x + 1e-15f); inv.y = 1.f / (den.y + 1e-15f);
    inv.z = 1.f / (den.z + 1e-15f); inv.w = 1.f / (den.w + 1e-15f);

#pragma unroll
    for (int e = 0; e < 8; e++) {
        float4 o = make_float4(0.f, 0.f, 0.f, 0.f);
#pragma unroll
        for (int d = 0; d < 8; d++) {
            float w = kvm[d * 9 + e];
            o.x += q[d].x * w; o.y += q[d].y * w;
            o.z += q[d].z * w; o.w += q[d].w * w;
        }
        float val[4] = {o.x * inv.x, o.y * inv.y, o.z * inv.z, o.w * inv.w};
        __half hh[4], ll[4];
#pragma unroll
        for (int j = 0; j < 4; j++) {
            hh[j] = __float2half_rn(val[j]);
            ll[j] = __float2half_rn(val[j] - __half2float(hh[j]));
        }
        __half2* ph = reinterpret_cast<__half2*>(&g_ath[dbase + e * HWN + hw]);
        __half2* pl = reinterpret_cast<__half2*>(&g_atl[dbase + e * HWN + hw]);
        ph[0] = __halves2half2(hh[0], hh[1]);
        ph[1] = __halves2half2(hh[2], hh[3]);
        pl[0] = __halves2half2(ll[0], ll[1]);
        pl[1] = __halves2half2(ll[2], ll[3]);
    }
}

// ===========================================================================
extern "C" void kernel_launch(void* const* d_in, const int* in_sizes, int n_in,
                              void* d_out, int out_size)
{
    const float* x      = (const float*)d_in[0];
    const float* w_qkv  = (const float*)d_in[1];
    const float* w_dw   = (const float*)d_in[2];
    const float* w_pw   = (const float*)d_in[3];
    const float* w_proj = (const float*)d_in[4];
    const float* gm     = (const float*)d_in[5];
    const float* bt     = (const float*)d_in[6];
    const float* mn     = (const float*)d_in[7];
    const float* vr     = (const float*)d_in[8];
    float* out = (float*)d_out;

    __half *xh, *xl, *ath, *atl, *wqh, *wql, *wph, *wpl, *qkvh;
    cudaGetSymbolAddress((void**)&qkvh, g_qkvh);
    cudaGetSymbolAddress((void**)&xh,  g_xh);
    cudaGetSymbolAddress((void**)&xl,  g_xl);
    cudaGetSymbolAddress((void**)&ath, g_ath);
    cudaGetSymbolAddress((void**)&atl, g_atl);
    cudaGetSymbolAddress((void**)&wqh, g_wqh);
    cudaGetSymbolAddress((void**)&wql, g_wql);
    cudaGetSymbolAddress((void**)&wph, g_wph);
    cudaGetSymbolAddress((void**)&wpl, g_wpl);

    cudaFuncSetAttribute(gemm_fp16x2<3, true>,
                         cudaFuncAttributeMaxDynamicSharedMemorySize, 89088);
    cudaFuncSetAttribute(gemm_fp16x2<4, false>,
                         cudaFuncAttributeMaxDynamicSharedMemorySize, 101376);

    // 0) one merged split launch (x, w_qkv, w_proj)
    int total4 = NX4 + NQ4 + NP4;
    split_all_k<<<(total4 + 255) / 256, 256>>>(
        x, w_qkv, w_proj,
        (__half2*)xh, (__half2*)xl, (__half2*)wqh, (__half2*)wql,
        (__half2*)wph, (__half2*)wpl);

    // 1) qkv GEMM [TM=96], half output
    gemm_fp16x2<3, true><<<dim3(32, 8, B_), 256, 89088>>>(
        wqh, wql, xh, xl, qkvh, 768, HWN, 256, nullptr, nullptr, nullptr, nullptr);
    // 2) fused dw 5x5 + grouped pw (half in/out)
    dwpw_k<<<dim3(4, 1, B_ * 96), 256>>>(w_dw, w_pw);
    // 3) attention (half inputs)
    att1_k<<<dim3(B_ * 64, 4), 128>>>();
    att2_k<<<dim3(B_ * 64, 8), 128>>>();
    // 4) proj + BN  [TM=128], fp32 output
    gemm_fp16x2<4, false><<<dim3(32, 2, B_), 256, 101376>>>(
        wph, wpl, ath, atl, out, 256, HWN, 512, gm, bt, mn, vr);
}